// round 1
// baseline (speedup 1.0000x reference)
#include <cuda_runtime.h>
#include <math.h>

#define B_   2
#define S_   2048
#define E_   1024
#define H_   16
#define D_   64
#define MTOT (B_*S_)   // 4096

// Scratch (allocation-free rule: __device__ globals)
__device__ float g_q[(size_t)B_*H_*S_*D_];
__device__ float g_k[(size_t)B_*H_*S_*D_];
__device__ float g_v[(size_t)B_*H_*S_*D_];
__device__ float g_attn[(size_t)MTOT*E_];

// ---------------------------------------------------------------------------
// GEMM: C = A * W^T + bias
// A: [M,K] row-major, W: [N,K] row-major (torch Linear convention)
// LAYOUT 0: C[m*N+n] plain   LAYOUT 1: scatter to q/k/v [B,H,S,D]
// ---------------------------------------------------------------------------
template<int LAYOUT>
__global__ __launch_bounds__(256)
void gemm_nt(const float* __restrict__ A,
             const float* __restrict__ W,
             const float* __restrict__ bias,
             float* __restrict__ C,
             int M, int N, int K)
{
    const int BM = 128, BN = 128, BK = 16;
    __shared__ float As[BK][BM];   // k-major (transposed)
    __shared__ float Ws[BK][BN];

    const int t  = threadIdx.x;
    const int tx = t & 15;         // 0..15  -> 8 cols each
    const int ty = t >> 4;         // 0..15  -> 8 rows each
    const int m0 = blockIdx.y * BM;
    const int n0 = blockIdx.x * BN;

    float acc[8][8];
    #pragma unroll
    for (int i = 0; i < 8; i++)
        #pragma unroll
        for (int j = 0; j < 8; j++) acc[i][j] = 0.f;

    for (int k0 = 0; k0 < K; k0 += BK) {
        // 128 rows x 16 k = 512 float4 per tile, 2 per thread
        #pragma unroll
        for (int i = 0; i < 2; i++) {
            int idx = t + i * 256;
            int row = idx >> 2;
            int k4  = idx & 3;
            float4 va = *reinterpret_cast<const float4*>(&A[(size_t)(m0 + row) * K + k0 + k4 * 4]);
            As[k4*4+0][row] = va.x; As[k4*4+1][row] = va.y;
            As[k4*4+2][row] = va.z; As[k4*4+3][row] = va.w;
            float4 vw = *reinterpret_cast<const float4*>(&W[(size_t)(n0 + row) * K + k0 + k4 * 4]);
            Ws[k4*4+0][row] = vw.x; Ws[k4*4+1][row] = vw.y;
            Ws[k4*4+2][row] = vw.z; Ws[k4*4+3][row] = vw.w;
        }
        __syncthreads();

        #pragma unroll
        for (int k = 0; k < BK; k++) {
            float a[8], bfr[8];
            *reinterpret_cast<float4*>(a)     = *reinterpret_cast<const float4*>(&As[k][ty*8]);
            *reinterpret_cast<float4*>(a + 4) = *reinterpret_cast<const float4*>(&As[k][ty*8+4]);
            *reinterpret_cast<float4*>(bfr)     = *reinterpret_cast<const float4*>(&Ws[k][tx*8]);
            *reinterpret_cast<float4*>(bfr + 4) = *reinterpret_cast<const float4*>(&Ws[k][tx*8+4]);
            #pragma unroll
            for (int i = 0; i < 8; i++)
                #pragma unroll
                for (int j = 0; j < 8; j++)
                    acc[i][j] += a[i] * bfr[j];
        }
        __syncthreads();
    }

    // epilogue
    #pragma unroll
    for (int i = 0; i < 8; i++) {
        int m = m0 + ty * 8 + i;
        #pragma unroll
        for (int j = 0; j < 8; j++) {
            int n = n0 + tx * 8 + j;
            float val = acc[i][j] + bias[n];
            if (LAYOUT == 0) {
                C[(size_t)m * N + n] = val;
            } else {
                int bb = m >> 11, s = m & 2047;   // S_=2048
                int hh = n >> 6,  d = n & 63;     // D_=64
                C[((((size_t)bb * H_ + hh) * S_ + s) << 6) + d] = val;
            }
        }
    }
}

// ---------------------------------------------------------------------------
// Flash attention with ALiBi + causal mask (fp32)
// grid = (S/64, H, B), block = 256. Tile: 64 queries x 64 keys, micro 4x4.
// smem: Qs[d][i] (64x68), Ks[d][j] (64x68, reused as P[j][i]), Vs[j][d] (64x64)
// ---------------------------------------------------------------------------
__global__ __launch_bounds__(256)
void flash_kernel(float* __restrict__ out)
{
    extern __shared__ float sm[];
    float* Qs = sm;                  // stride 68, d-major
    float* Ks = sm + 64 * 68;        // stride 68, d-major; reused as Ps[j][i]
    float* Vs = sm + 2 * 64 * 68;    // stride 64, j-major

    const int t  = threadIdx.x;
    const int tx = t & 15;           // key / headdim cols (4 each)
    const int ty = t >> 4;           // query rows (4 each)
    const int qt = blockIdx.x;
    const int h  = blockIdx.y;
    const int b  = blockIdx.z;

    const float* qbase = g_q + (((size_t)b * H_ + h) * S_ + qt * 64) * D_;
    const float* kb0   = g_k + (((size_t)b * H_ + h) * S_) * D_;
    const float* vb0   = g_v + (((size_t)b * H_ + h) * S_) * D_;

    const float slope  = exp2f(-0.5f * (float)(h + 1));  // H=16 power of 2
    const float scaleD = 0.125f;                          // 1/sqrt(64)

    // load Q tile transposed (d-major)
    #pragma unroll
    for (int i = 0; i < 4; i++) {
        int idx = t + i * 256;
        int row = idx >> 4;
        int d4  = idx & 15;
        float4 v = *reinterpret_cast<const float4*>(&qbase[row * 64 + d4 * 4]);
        Qs[(d4*4+0)*68 + row] = v.x; Qs[(d4*4+1)*68 + row] = v.y;
        Qs[(d4*4+2)*68 + row] = v.z; Qs[(d4*4+3)*68 + row] = v.w;
    }

    float m_r[4], l_r[4], o[4][4];
    #pragma unroll
    for (int r = 0; r < 4; r++) {
        m_r[r] = -1e30f; l_r[r] = 0.f;
        #pragma unroll
        for (int c = 0; c < 4; c++) o[r][c] = 0.f;
    }

    const int q_lo = qt * 64;

    for (int kt = 0; kt <= qt; kt++) {
        const float* kbase = kb0 + (size_t)kt * 64 * 64;
        const float* vbase = vb0 + (size_t)kt * 64 * 64;

        // load K transposed + V natural
        #pragma unroll
        for (int i = 0; i < 4; i++) {
            int idx = t + i * 256;
            int row = idx >> 4;
            int d4  = idx & 15;
            float4 kv = *reinterpret_cast<const float4*>(&kbase[row * 64 + d4 * 4]);
            Ks[(d4*4+0)*68 + row] = kv.x; Ks[(d4*4+1)*68 + row] = kv.y;
            Ks[(d4*4+2)*68 + row] = kv.z; Ks[(d4*4+3)*68 + row] = kv.w;
            float4 vv = *reinterpret_cast<const float4*>(&vbase[row * 64 + d4 * 4]);
            *reinterpret_cast<float4*>(&Vs[row * 64 + d4 * 4]) = vv;
        }
        __syncthreads();

        // S = Q K^T
        float s[4][4];
        #pragma unroll
        for (int r = 0; r < 4; r++)
            #pragma unroll
            for (int c = 0; c < 4; c++) s[r][c] = 0.f;

        #pragma unroll 8
        for (int d = 0; d < 64; d++) {
            float a[4], kk[4];
            *reinterpret_cast<float4*>(a)  = *reinterpret_cast<const float4*>(&Qs[d * 68 + ty * 4]);
            *reinterpret_cast<float4*>(kk) = *reinterpret_cast<const float4*>(&Ks[d * 68 + tx * 4]);
            #pragma unroll
            for (int r = 0; r < 4; r++)
                #pragma unroll
                for (int c = 0; c < 4; c++)
                    s[r][c] += a[r] * kk[c];
        }

        // scale + ALiBi + causal mask + online softmax
        float p[4][4];
        #pragma unroll
        for (int r = 0; r < 4; r++) {
            const int qi = q_lo + ty * 4 + r;
            float rowm = -1e30f;
            #pragma unroll
            for (int c = 0; c < 4; c++) {
                int kj = kt * 64 + tx * 4 + c;
                float sv = (kj <= qi)
                         ? (s[r][c] * scaleD - slope * (float)(qi - kj))
                         : -1e30f;
                s[r][c] = sv;
                rowm = fmaxf(rowm, sv);
            }
            #pragma unroll
            for (int off = 1; off < 16; off <<= 1)
                rowm = fmaxf(rowm, __shfl_xor_sync(0xffffffffu, rowm, off));
            float mnew  = fmaxf(m_r[r], rowm);
            float alpha = __expf(m_r[r] - mnew);
            float rs = 0.f;
            #pragma unroll
            for (int c = 0; c < 4; c++) {
                float pv = __expf(s[r][c] - mnew);
                p[r][c] = pv;
                rs += pv;
            }
            #pragma unroll
            for (int off = 1; off < 16; off <<= 1)
                rs += __shfl_xor_sync(0xffffffffu, rs, off);
            l_r[r] = l_r[r] * alpha + rs;
            m_r[r] = mnew;
            #pragma unroll
            for (int c = 0; c < 4; c++) o[r][c] *= alpha;
        }

        __syncthreads();   // everyone done reading Ks
        // write P transposed into Ks region: Ps[j][i]
        #pragma unroll
        for (int c = 0; c < 4; c++)
            #pragma unroll
            for (int r = 0; r < 4; r++)
                Ks[(tx * 4 + c) * 68 + ty * 4 + r] = p[r][c];
        __syncthreads();

        // O += P V
        #pragma unroll 8
        for (int j = 0; j < 64; j++) {
            float a[4], vv[4];
            *reinterpret_cast<float4*>(a)  = *reinterpret_cast<const float4*>(&Ks[j * 68 + ty * 4]);
            *reinterpret_cast<float4*>(vv) = *reinterpret_cast<const float4*>(&Vs[j * 64 + tx * 4]);
            #pragma unroll
            for (int r = 0; r < 4; r++)
                #pragma unroll
                for (int c = 0; c < 4; c++)
                    o[r][c] += a[r] * vv[c];
        }
        __syncthreads();
    }

    // normalize and write [B,S,E]
    #pragma unroll
    for (int r = 0; r < 4; r++) {
        float inv = 1.f / l_r[r];
        int srow = q_lo + ty * 4 + r;
        float4 ov;
        ov.x = o[r][0] * inv; ov.y = o[r][1] * inv;
        ov.z = o[r][2] * inv; ov.w = o[r][3] * inv;
        *reinterpret_cast<float4*>(&out[((size_t)b * S_ + srow) * E_ + h * 64 + tx * 4]) = ov;
    }
}

// ---------------------------------------------------------------------------
extern "C" void kernel_launch(void* const* d_in, const int* in_sizes, int n_in,
                              void* d_out, int out_size)
{
    const float* x  = (const float*)d_in[0];
    const float* Wq = (const float*)d_in[1];
    const float* bq = (const float*)d_in[2];
    const float* Wk = (const float*)d_in[3];
    const float* bk = (const float*)d_in[4];
    const float* Wv = (const float*)d_in[5];
    const float* bv = (const float*)d_in[6];
    const float* Wo = (const float*)d_in[7];
    const float* bo = (const float*)d_in[8];
    float* out = (float*)d_out;

    float *qp, *kp, *vp, *ap;
    cudaGetSymbolAddress((void**)&qp, g_q);
    cudaGetSymbolAddress((void**)&kp, g_k);
    cudaGetSymbolAddress((void**)&vp, g_v);
    cudaGetSymbolAddress((void**)&ap, g_attn);

    const int SMEM_FLASH = (2 * 64 * 68 + 64 * 64) * (int)sizeof(float);  // 51200 B
    cudaFuncSetAttribute(flash_kernel, cudaFuncAttributeMaxDynamicSharedMemorySize, SMEM_FLASH);

    dim3 gblk(256);
    dim3 ggrid(E_ / 128, MTOT / 128);

    gemm_nt<1><<<ggrid, gblk>>>(x, Wq, bq, qp, MTOT, E_, E_);
    gemm_nt<1><<<ggrid, gblk>>>(x, Wk, bk, kp, MTOT, E_, E_);
    gemm_nt<1><<<ggrid, gblk>>>(x, Wv, bv, vp, MTOT, E_, E_);

    dim3 fgrid(S_ / 64, H_, B_);
    flash_kernel<<<fgrid, 256, SMEM_FLASH>>>(ap);

    gemm_nt<0><<<ggrid, gblk>>>(ap, Wo, bo, out, MTOT, E_, E_);
}

// round 3
// speedup vs baseline: 1.6411x; 1.6411x over previous
#include <cuda_runtime.h>
#include <cuda_bf16.h>
#include <math.h>
#include <stdint.h>

#define B_   2
#define S_   2048
#define E_   1024
#define H_   16
#define D_   64
#define MTOT (B_*S_)   // 4096

// Scratch (allocation-free rule: __device__ globals)
__device__ float g_q[(size_t)B_*H_*S_*D_];
__device__ float g_k[(size_t)B_*H_*S_*D_];
__device__ float g_v[(size_t)B_*H_*S_*D_];
__device__ float g_attn[(size_t)MTOT*E_];

// ---------------------------------------------------------------------------
// Warp-MMA helpers (baseline PTX, compiles on plain compute_103)
// ---------------------------------------------------------------------------
__device__ __forceinline__ uint32_t smem_u32(const void* p) {
    uint32_t a;
    asm("{ .reg .u64 t; cvta.to.shared.u64 t, %1; cvt.u32.u64 %0, t; }"
        : "=r"(a) : "l"(p));
    return a;
}
__device__ __forceinline__ void ldsm_x4(uint32_t r[4], uint32_t addr) {
    asm volatile("ldmatrix.sync.aligned.m8n8.x4.shared.b16 {%0,%1,%2,%3}, [%4];"
        : "=r"(r[0]), "=r"(r[1]), "=r"(r[2]), "=r"(r[3]) : "r"(addr));
}
__device__ __forceinline__ void mma_bf16(float c[4], const uint32_t a[4],
                                         uint32_t b0, uint32_t b1) {
    asm volatile("mma.sync.aligned.m16n8k16.row.col.f32.bf16.bf16.f32 "
        "{%0,%1,%2,%3}, {%4,%5,%6,%7}, {%8,%9}, {%0,%1,%2,%3};"
        : "+f"(c[0]), "+f"(c[1]), "+f"(c[2]), "+f"(c[3])
        : "r"(a[0]), "r"(a[1]), "r"(a[2]), "r"(a[3]), "r"(b0), "r"(b1));
}
__device__ __forceinline__ uint32_t bf2_pack(float x, float y) {
    __nv_bfloat162 h = __floats2bfloat162_rn(x, y);
    return *reinterpret_cast<uint32_t*>(&h);
}

// ---------------------------------------------------------------------------
// bf16x3 tensor-core GEMM:  C = A * W^T + bias
// A: [M,1024] fp32, W: [1024,1024] fp32 (torch Linear). M = 4096.
// CTA tile 128x128, 256 threads (8 warps), warp tile 64x32 (4x4 m16n8k16).
// K chunk = 32 fp32 -> smem rows [hi(32 bf16) | lo(32 bf16)], stride 72.
// 3-term product: hi*hi + hi*lo + lo*hi  (~1e-5 rel accuracy).
// LAYOUT 0: C[m*1024+n]   LAYOUT 1: scatter to [B,H,S,D]
// blockIdx.z selects (W,b,C) set: fused QKV uses z=3.
// ---------------------------------------------------------------------------
#define SAST 72           // smem row stride in bf16 elements (144 bytes)
#define SAB  (128*SAST*2) // bytes per operand tile: 18432

template<int LAYOUT>
__global__ __launch_bounds__(256)
void hmma_gemm(const float* __restrict__ A,
               const float* __restrict__ W0, const float* __restrict__ W1,
               const float* __restrict__ W2,
               const float* __restrict__ b0p, const float* __restrict__ b1p,
               const float* __restrict__ b2p,
               float* __restrict__ C0, float* __restrict__ C1,
               float* __restrict__ C2)
{
    extern __shared__ char smem[];
    __nv_bfloat16* sAp = reinterpret_cast<__nv_bfloat16*>(smem);
    __nv_bfloat16* sBp = reinterpret_cast<__nv_bfloat16*>(smem + SAB);
    const uint32_t sA = smem_u32(sAp);
    const uint32_t sB = smem_u32(sBp);

    const int z = blockIdx.z;
    const float* W    = (z == 0) ? W0 : (z == 1) ? W1 : W2;
    const float* bias = (z == 0) ? b0p : (z == 1) ? b1p : b2p;
    float*       C    = (z == 0) ? C0 : (z == 1) ? C1 : C2;

    const int t   = threadIdx.x;
    const int w   = t >> 5;
    const int l   = t & 31;
    const int wy  = w >> 2;          // 0..1
    const int wx  = w & 3;           // 0..3
    const int m0  = blockIdx.y * 128;
    const int n0  = blockIdx.x * 128;
    const int K   = E_;

    float acc[4][4][4];
    #pragma unroll
    for (int i = 0; i < 4; i++)
        #pragma unroll
        for (int j = 0; j < 4; j++) {
            acc[i][j][0] = 0.f; acc[i][j][1] = 0.f;
            acc[i][j][2] = 0.f; acc[i][j][3] = 0.f;
        }

    // precomputed ldmatrix lane addresses (byte offsets within tile)
    const uint32_t a_row = (uint32_t)(l & 15);
    const uint32_t a_koff = (l & 16) ? 8u : 0u;
    const uint32_t b_row = (uint32_t)((l & 7) + ((l & 16) ? 8 : 0));
    const uint32_t b_koff = (l & 8) ? 8u : 0u;

    for (int k0 = 0; k0 < K; k0 += 32) {
        // ---- load 32 fp32 per row (4 float4 per thread per operand)
        float4 va[4], vb[4];
        #pragma unroll
        for (int i = 0; i < 4; i++) {
            int idx = t + i * 256;          // 0..1023
            int row = idx >> 3;
            int c4  = idx & 7;
            va[i] = *reinterpret_cast<const float4*>(&A[(size_t)(m0 + row) * K + k0 + c4 * 4]);
            vb[i] = *reinterpret_cast<const float4*>(&W[(size_t)(n0 + row) * K + k0 + c4 * 4]);
        }
        __syncthreads();   // previous chunk fully consumed

        // ---- split to bf16 hi/lo and store
        #pragma unroll
        for (int i = 0; i < 4; i++) {
            int idx = t + i * 256;
            int row = idx >> 3;
            int c4  = idx & 7;
            {
                float4 v = va[i];
                float hx = __bfloat162float(__float2bfloat16_rn(v.x));
                float hy = __bfloat162float(__float2bfloat16_rn(v.y));
                float hz = __bfloat162float(__float2bfloat16_rn(v.z));
                float hw = __bfloat162float(__float2bfloat16_rn(v.w));
                uint2 hi = { bf2_pack(hx, hy), bf2_pack(hz, hw) };
                uint2 lo = { bf2_pack(v.x - hx, v.y - hy), bf2_pack(v.z - hz, v.w - hw) };
                *reinterpret_cast<uint2*>(&sAp[row * SAST + c4 * 4])      = hi;
                *reinterpret_cast<uint2*>(&sAp[row * SAST + 32 + c4 * 4]) = lo;
            }
            {
                float4 v = vb[i];
                float hx = __bfloat162float(__float2bfloat16_rn(v.x));
                float hy = __bfloat162float(__float2bfloat16_rn(v.y));
                float hz = __bfloat162float(__float2bfloat16_rn(v.z));
                float hw = __bfloat162float(__float2bfloat16_rn(v.w));
                uint2 hi = { bf2_pack(hx, hy), bf2_pack(hz, hw) };
                uint2 lo = { bf2_pack(v.x - hx, v.y - hy), bf2_pack(v.z - hz, v.w - hw) };
                *reinterpret_cast<uint2*>(&sBp[row * SAST + c4 * 4])      = hi;
                *reinterpret_cast<uint2*>(&sBp[row * SAST + 32 + c4 * 4]) = lo;
            }
        }
        __syncthreads();

        // ---- 6 k16-steps: (ka,kb) in {(0,0),(0,2),(1,1),(1,3),(2,0),(3,1)}
        // k-groups: 0,1 = hi halves; 2,3 = lo halves
        #pragma unroll
        for (int ka = 0; ka < 4; ka++) {
            uint32_t af[4][4];
            #pragma unroll
            for (int mi = 0; mi < 4; mi++) {
                uint32_t row = (uint32_t)(wy * 64 + mi * 16) + a_row;
                uint32_t col = (uint32_t)(ka * 16) + a_koff;
                ldsm_x4(af[mi], sA + row * (SAST * 2) + col * 2);
            }
            const int nkb   = (ka < 2) ? 2 : 1;
            const int kbl0  = (ka == 0) ? 0 : (ka == 1) ? 1 : (ka == 2) ? 0 : 1;
            const int kbl1  = (ka == 0) ? 2 : 3;
            #pragma unroll
            for (int j = 0; j < 2; j++) {
                if (j >= nkb) break;
                const int kb = (j == 0) ? kbl0 : kbl1;
                #pragma unroll
                for (int nb = 0; nb < 2; nb++) {
                    uint32_t bf[4];
                    uint32_t row = (uint32_t)(wx * 32 + nb * 16) + b_row;
                    uint32_t col = (uint32_t)(kb * 16) + b_koff;
                    ldsm_x4(bf, sB + row * (SAST * 2) + col * 2);
                    #pragma unroll
                    for (int mi = 0; mi < 4; mi++) {
                        mma_bf16(acc[mi][nb * 2 + 0], af[mi], bf[0], bf[1]);
                        mma_bf16(acc[mi][nb * 2 + 1], af[mi], bf[2], bf[3]);
                    }
                }
            }
        }
    }

    // ---- epilogue: D fragment -> bias add -> store
    #pragma unroll
    for (int mi = 0; mi < 4; mi++) {
        #pragma unroll
        for (int ni = 0; ni < 4; ni++) {
            int n = n0 + wx * 32 + ni * 8 + 2 * (l & 3);
            float2 bv = *reinterpret_cast<const float2*>(&bias[n]);
            #pragma unroll
            for (int half = 0; half < 2; half++) {
                int m = m0 + wy * 64 + mi * 16 + (l >> 2) + half * 8;
                float2 ov;
                ov.x = acc[mi][ni][half * 2 + 0] + bv.x;
                ov.y = acc[mi][ni][half * 2 + 1] + bv.y;
                if (LAYOUT == 0) {
                    *reinterpret_cast<float2*>(&C[(size_t)m * E_ + n]) = ov;
                } else {
                    int bb = m >> 11, s = m & 2047;
                    int hh = n >> 6,  d = n & 63;
                    *reinterpret_cast<float2*>(
                        &C[((((size_t)bb * H_ + hh) * S_ + s) << 6) + d]) = ov;
                }
            }
        }
    }
}

// ---------------------------------------------------------------------------
// Flash attention with ALiBi + causal mask (fp32) — unchanged from R1
// ---------------------------------------------------------------------------
__global__ __launch_bounds__(256)
void flash_kernel(float* __restrict__ out)
{
    extern __shared__ float sm[];
    float* Qs = sm;
    float* Ks = sm + 64 * 68;
    float* Vs = sm + 2 * 64 * 68;

    const int t  = threadIdx.x;
    const int tx = t & 15;
    const int ty = t >> 4;
    const int qt = blockIdx.x;
    const int h  = blockIdx.y;
    const int b  = blockIdx.z;

    const float* qbase = g_q + (((size_t)b * H_ + h) * S_ + qt * 64) * D_;
    const float* kb0   = g_k + (((size_t)b * H_ + h) * S_) * D_;
    const float* vb0   = g_v + (((size_t)b * H_ + h) * S_) * D_;

    const float slope  = exp2f(-0.5f * (float)(h + 1));
    const float scaleD = 0.125f;

    #pragma unroll
    for (int i = 0; i < 4; i++) {
        int idx = t + i * 256;
        int row = idx >> 4;
        int d4  = idx & 15;
        float4 v = *reinterpret_cast<const float4*>(&qbase[row * 64 + d4 * 4]);
        Qs[(d4*4+0)*68 + row] = v.x; Qs[(d4*4+1)*68 + row] = v.y;
        Qs[(d4*4+2)*68 + row] = v.z; Qs[(d4*4+3)*68 + row] = v.w;
    }

    float m_r[4], l_r[4], o[4][4];
    #pragma unroll
    for (int r = 0; r < 4; r++) {
        m_r[r] = -1e30f; l_r[r] = 0.f;
        #pragma unroll
        for (int c = 0; c < 4; c++) o[r][c] = 0.f;
    }

    const int q_lo = qt * 64;

    for (int kt = 0; kt <= qt; kt++) {
        const float* kbase = kb0 + (size_t)kt * 64 * 64;
        const float* vbase = vb0 + (size_t)kt * 64 * 64;

        #pragma unroll
        for (int i = 0; i < 4; i++) {
            int idx = t + i * 256;
            int row = idx >> 4;
            int d4  = idx & 15;
            float4 kv = *reinterpret_cast<const float4*>(&kbase[row * 64 + d4 * 4]);
            Ks[(d4*4+0)*68 + row] = kv.x; Ks[(d4*4+1)*68 + row] = kv.y;
            Ks[(d4*4+2)*68 + row] = kv.z; Ks[(d4*4+3)*68 + row] = kv.w;
            float4 vv = *reinterpret_cast<const float4*>(&vbase[row * 64 + d4 * 4]);
            *reinterpret_cast<float4*>(&Vs[row * 64 + d4 * 4]) = vv;
        }
        __syncthreads();

        float s[4][4];
        #pragma unroll
        for (int r = 0; r < 4; r++)
            #pragma unroll
            for (int c = 0; c < 4; c++) s[r][c] = 0.f;

        #pragma unroll 8
        for (int d = 0; d < 64; d++) {
            float a[4], kk[4];
            *reinterpret_cast<float4*>(a)  = *reinterpret_cast<const float4*>(&Qs[d * 68 + ty * 4]);
            *reinterpret_cast<float4*>(kk) = *reinterpret_cast<const float4*>(&Ks[d * 68 + tx * 4]);
            #pragma unroll
            for (int r = 0; r < 4; r++)
                #pragma unroll
                for (int c = 0; c < 4; c++)
                    s[r][c] += a[r] * kk[c];
        }

        float p[4][4];
        #pragma unroll
        for (int r = 0; r < 4; r++) {
            const int qi = q_lo + ty * 4 + r;
            float rowm = -1e30f;
            #pragma unroll
            for (int c = 0; c < 4; c++) {
                int kj = kt * 64 + tx * 4 + c;
                float sv = (kj <= qi)
                         ? (s[r][c] * scaleD - slope * (float)(qi - kj))
                         : -1e30f;
                s[r][c] = sv;
                rowm = fmaxf(rowm, sv);
            }
            #pragma unroll
            for (int off = 1; off < 16; off <<= 1)
                rowm = fmaxf(rowm, __shfl_xor_sync(0xffffffffu, rowm, off));
            float mnew  = fmaxf(m_r[r], rowm);
            float alpha = __expf(m_r[r] - mnew);
            float rs = 0.f;
            #pragma unroll
            for (int c = 0; c < 4; c++) {
                float pv = __expf(s[r][c] - mnew);
                p[r][c] = pv;
                rs += pv;
            }
            #pragma unroll
            for (int off = 1; off < 16; off <<= 1)
                rs += __shfl_xor_sync(0xffffffffu, rs, off);
            l_r[r] = l_r[r] * alpha + rs;
            m_r[r] = mnew;
            #pragma unroll
            for (int c = 0; c < 4; c++) o[r][c] *= alpha;
        }

        __syncthreads();
        #pragma unroll
        for (int c = 0; c < 4; c++)
            #pragma unroll
            for (int r = 0; r < 4; r++)
                Ks[(tx * 4 + c) * 68 + ty * 4 + r] = p[r][c];
        __syncthreads();

        #pragma unroll 8
        for (int j = 0; j < 64; j++) {
            float a[4], vv[4];
            *reinterpret_cast<float4*>(a)  = *reinterpret_cast<const float4*>(&Ks[j * 68 + ty * 4]);
            *reinterpret_cast<float4*>(vv) = *reinterpret_cast<const float4*>(&Vs[j * 64 + tx * 4]);
            #pragma unroll
            for (int r = 0; r < 4; r++)
                #pragma unroll
                for (int c = 0; c < 4; c++)
                    o[r][c] += a[r] * vv[c];
        }
        __syncthreads();
    }

    #pragma unroll
    for (int r = 0; r < 4; r++) {
        float inv = 1.f / l_r[r];
        int srow = q_lo + ty * 4 + r;
        float4 ov;
        ov.x = o[r][0] * inv; ov.y = o[r][1] * inv;
        ov.z = o[r][2] * inv; ov.w = o[r][3] * inv;
        *reinterpret_cast<float4*>(&out[((size_t)b * S_ + srow) * E_ + h * 64 + tx * 4]) = ov;
    }
}

// ---------------------------------------------------------------------------
extern "C" void kernel_launch(void* const* d_in, const int* in_sizes, int n_in,
                              void* d_out, int out_size)
{
    const float* x  = (const float*)d_in[0];
    const float* Wq = (const float*)d_in[1];
    const float* bq = (const float*)d_in[2];
    const float* Wk = (const float*)d_in[3];
    const float* bk = (const float*)d_in[4];
    const float* Wv = (const float*)d_in[5];
    const float* bv = (const float*)d_in[6];
    const float* Wo = (const float*)d_in[7];
    const float* bo = (const float*)d_in[8];
    float* out = (float*)d_out;

    float *qp, *kp, *vp, *ap;
    cudaGetSymbolAddress((void**)&qp, g_q);
    cudaGetSymbolAddress((void**)&kp, g_k);
    cudaGetSymbolAddress((void**)&vp, g_v);
    cudaGetSymbolAddress((void**)&ap, g_attn);

    const int SMEM_FLASH = (2 * 64 * 68 + 64 * 64) * (int)sizeof(float);  // 51200 B
    cudaFuncSetAttribute(flash_kernel, cudaFuncAttributeMaxDynamicSharedMemorySize, SMEM_FLASH);

    const int SMEM_GEMM = 2 * SAB;   // 36864 B
    cudaFuncSetAttribute(hmma_gemm<0>, cudaFuncAttributeMaxDynamicSharedMemorySize, SMEM_GEMM);
    cudaFuncSetAttribute(hmma_gemm<1>, cudaFuncAttributeMaxDynamicSharedMemorySize, SMEM_GEMM);

    // fused Q/K/V projections
    dim3 qkv_grid(E_ / 128, MTOT / 128, 3);   // (8, 32, 3)
    hmma_gemm<1><<<qkv_grid, 256, SMEM_GEMM>>>(x, Wq, Wk, Wv, bq, bk, bv, qp, kp, vp);

    dim3 fgrid(S_ / 64, H_, B_);
    flash_kernel<<<fgrid, 256, SMEM_FLASH>>>(ap);

    // output projection
    dim3 o_grid(E_ / 128, MTOT / 128, 1);
    hmma_gemm<0><<<o_grid, 256, SMEM_GEMM>>>(ap, Wo, Wo, Wo, bo, bo, bo, out, out, out);
}

// round 4
// speedup vs baseline: 3.1969x; 1.9480x over previous
#include <cuda_runtime.h>
#include <cuda_bf16.h>
#include <math.h>
#include <stdint.h>

#define B_   2
#define S_   2048
#define E_   1024
#define H_   16
#define D_   64
#define MTOT (B_*S_)   // 4096
#define QSZ_ ((size_t)B_*H_*S_*D_)   // 4194304

// Scratch (allocation-free rule: __device__ globals)
// q/k/v stored as bf16 hi (first QSZ_) + lo (second QSZ_), layout [B,H,S,D]
__device__ __align__(16) __nv_bfloat16 g_qb[2*QSZ_];
__device__ __align__(16) __nv_bfloat16 g_kb[2*QSZ_];
__device__ __align__(16) __nv_bfloat16 g_vb[2*QSZ_];
__device__ float g_attn[(size_t)MTOT*E_];

// ---------------------------------------------------------------------------
// Warp-MMA helpers (baseline PTX, compiles on plain compute_103)
// ---------------------------------------------------------------------------
__device__ __forceinline__ uint32_t smem_u32(const void* p) {
    uint32_t a;
    asm("{ .reg .u64 t; cvta.to.shared.u64 t, %1; cvt.u32.u64 %0, t; }"
        : "=r"(a) : "l"(p));
    return a;
}
__device__ __forceinline__ void ldsm_x4(uint32_t r[4], uint32_t addr) {
    asm volatile("ldmatrix.sync.aligned.m8n8.x4.shared.b16 {%0,%1,%2,%3}, [%4];"
        : "=r"(r[0]), "=r"(r[1]), "=r"(r[2]), "=r"(r[3]) : "r"(addr));
}
__device__ __forceinline__ void ldsm_x4_t(uint32_t r[4], uint32_t addr) {
    asm volatile("ldmatrix.sync.aligned.m8n8.x4.trans.shared.b16 {%0,%1,%2,%3}, [%4];"
        : "=r"(r[0]), "=r"(r[1]), "=r"(r[2]), "=r"(r[3]) : "r"(addr));
}
__device__ __forceinline__ void mma_bf16(float c[4], const uint32_t a[4],
                                         uint32_t b0, uint32_t b1) {
    asm volatile("mma.sync.aligned.m16n8k16.row.col.f32.bf16.bf16.f32 "
        "{%0,%1,%2,%3}, {%4,%5,%6,%7}, {%8,%9}, {%0,%1,%2,%3};"
        : "+f"(c[0]), "+f"(c[1]), "+f"(c[2]), "+f"(c[3])
        : "r"(a[0]), "r"(a[1]), "r"(a[2]), "r"(a[3]), "r"(b0), "r"(b1));
}
__device__ __forceinline__ uint32_t bf2_pack(float x, float y) {
    __nv_bfloat162 h = __floats2bfloat162_rn(x, y);
    return *reinterpret_cast<uint32_t*>(&h);
}

// ---------------------------------------------------------------------------
// bf16x3 tensor-core GEMM:  C = (A * W^T + bias) [* scl]
// CTA tile 128x128, 256 threads (8 warps), warp tile 64x32 (4x4 m16n8k16).
// 3-term: hi*hi + hi*lo + lo*hi.
// LAYOUT 0: fp32 out C[m*1024+n]
// LAYOUT 1: bf16 hi/lo out, scattered [B,H,S,D]; z selects q(scale 1/8)/k/v
// ---------------------------------------------------------------------------
#define SAST 72           // smem row stride in bf16 elements (144 bytes)
#define SAB  (128*SAST*2) // bytes per operand tile: 18432

template<int LAYOUT>
__global__ __launch_bounds__(256)
void hmma_gemm(const float* __restrict__ A,
               const float* __restrict__ W0, const float* __restrict__ W1,
               const float* __restrict__ W2,
               const float* __restrict__ b0p, const float* __restrict__ b1p,
               const float* __restrict__ b2p,
               void* __restrict__ C0v, void* __restrict__ C1v,
               void* __restrict__ C2v)
{
    extern __shared__ char smem[];
    __nv_bfloat16* sAp = reinterpret_cast<__nv_bfloat16*>(smem);
    __nv_bfloat16* sBp = reinterpret_cast<__nv_bfloat16*>(smem + SAB);
    const uint32_t sA = smem_u32(sAp);
    const uint32_t sB = smem_u32(sBp);

    const int z = blockIdx.z;
    const float* W    = (z == 0) ? W0 : (z == 1) ? W1 : W2;
    const float* bias = (z == 0) ? b0p : (z == 1) ? b1p : b2p;
    void*        Cv   = (z == 0) ? C0v : (z == 1) ? C1v : C2v;
    const float  scl  = (LAYOUT == 1 && z == 0) ? 0.125f : 1.0f;

    const int t   = threadIdx.x;
    const int w   = t >> 5;
    const int l   = t & 31;
    const int wy  = w >> 2;          // 0..1
    const int wx  = w & 3;           // 0..3
    const int m0  = blockIdx.y * 128;
    const int n0  = blockIdx.x * 128;
    const int K   = E_;

    float acc[4][4][4];
    #pragma unroll
    for (int i = 0; i < 4; i++)
        #pragma unroll
        for (int j = 0; j < 4; j++) {
            acc[i][j][0] = 0.f; acc[i][j][1] = 0.f;
            acc[i][j][2] = 0.f; acc[i][j][3] = 0.f;
        }

    const uint32_t a_row  = (uint32_t)(l & 15);
    const uint32_t a_koff = (l & 16) ? 8u : 0u;
    const uint32_t b_row  = (uint32_t)((l & 7) + ((l & 16) ? 8 : 0));
    const uint32_t b_koff = (l & 8) ? 8u : 0u;

    for (int k0 = 0; k0 < K; k0 += 32) {
        float4 va[4], vb[4];
        #pragma unroll
        for (int i = 0; i < 4; i++) {
            int idx = t + i * 256;
            int row = idx >> 3;
            int c4  = idx & 7;
            va[i] = *reinterpret_cast<const float4*>(&A[(size_t)(m0 + row) * K + k0 + c4 * 4]);
            vb[i] = *reinterpret_cast<const float4*>(&W[(size_t)(n0 + row) * K + k0 + c4 * 4]);
        }
        __syncthreads();

        #pragma unroll
        for (int i = 0; i < 4; i++) {
            int idx = t + i * 256;
            int row = idx >> 3;
            int c4  = idx & 7;
            {
                float4 v = va[i];
                float hx = __bfloat162float(__float2bfloat16_rn(v.x));
                float hy = __bfloat162float(__float2bfloat16_rn(v.y));
                float hz = __bfloat162float(__float2bfloat16_rn(v.z));
                float hw = __bfloat162float(__float2bfloat16_rn(v.w));
                uint2 hi = { bf2_pack(hx, hy), bf2_pack(hz, hw) };
                uint2 lo = { bf2_pack(v.x - hx, v.y - hy), bf2_pack(v.z - hz, v.w - hw) };
                *reinterpret_cast<uint2*>(&sAp[row * SAST + c4 * 4])      = hi;
                *reinterpret_cast<uint2*>(&sAp[row * SAST + 32 + c4 * 4]) = lo;
            }
            {
                float4 v = vb[i];
                float hx = __bfloat162float(__float2bfloat16_rn(v.x));
                float hy = __bfloat162float(__float2bfloat16_rn(v.y));
                float hz = __bfloat162float(__float2bfloat16_rn(v.z));
                float hw = __bfloat162float(__float2bfloat16_rn(v.w));
                uint2 hi = { bf2_pack(hx, hy), bf2_pack(hz, hw) };
                uint2 lo = { bf2_pack(v.x - hx, v.y - hy), bf2_pack(v.z - hz, v.w - hw) };
                *reinterpret_cast<uint2*>(&sBp[row * SAST + c4 * 4])      = hi;
                *reinterpret_cast<uint2*>(&sBp[row * SAST + 32 + c4 * 4]) = lo;
            }
        }
        __syncthreads();

        #pragma unroll
        for (int ka = 0; ka < 4; ka++) {
            uint32_t af[4][4];
            #pragma unroll
            for (int mi = 0; mi < 4; mi++) {
                uint32_t row = (uint32_t)(wy * 64 + mi * 16) + a_row;
                uint32_t col = (uint32_t)(ka * 16) + a_koff;
                ldsm_x4(af[mi], sA + row * (SAST * 2) + col * 2);
            }
            const int nkb   = (ka < 2) ? 2 : 1;
            const int kbl0  = (ka == 0) ? 0 : (ka == 1) ? 1 : (ka == 2) ? 0 : 1;
            const int kbl1  = (ka == 0) ? 2 : 3;
            #pragma unroll
            for (int j = 0; j < 2; j++) {
                if (j >= nkb) break;
                const int kb = (j == 0) ? kbl0 : kbl1;
                #pragma unroll
                for (int nb = 0; nb < 2; nb++) {
                    uint32_t bf[4];
                    uint32_t row = (uint32_t)(wx * 32 + nb * 16) + b_row;
                    uint32_t col = (uint32_t)(kb * 16) + b_koff;
                    ldsm_x4(bf, sB + row * (SAST * 2) + col * 2);
                    #pragma unroll
                    for (int mi = 0; mi < 4; mi++) {
                        mma_bf16(acc[mi][nb * 2 + 0], af[mi], bf[0], bf[1]);
                        mma_bf16(acc[mi][nb * 2 + 1], af[mi], bf[2], bf[3]);
                    }
                }
            }
        }
    }

    // ---- epilogue
    #pragma unroll
    for (int mi = 0; mi < 4; mi++) {
        #pragma unroll
        for (int ni = 0; ni < 4; ni++) {
            int n = n0 + wx * 32 + ni * 8 + 2 * (l & 3);
            float2 bv = *reinterpret_cast<const float2*>(&bias[n]);
            #pragma unroll
            for (int half = 0; half < 2; half++) {
                int m = m0 + wy * 64 + mi * 16 + (l >> 2) + half * 8;
                float vx = acc[mi][ni][half * 2 + 0] + bv.x;
                float vy = acc[mi][ni][half * 2 + 1] + bv.y;
                if (LAYOUT == 0) {
                    float* C = (float*)Cv;
                    float2 ov; ov.x = vx; ov.y = vy;
                    *reinterpret_cast<float2*>(&C[(size_t)m * E_ + n]) = ov;
                } else {
                    vx *= scl; vy *= scl;
                    __nv_bfloat16* Cb = (__nv_bfloat16*)Cv;
                    float hx = __bfloat162float(__float2bfloat16_rn(vx));
                    float hy = __bfloat162float(__float2bfloat16_rn(vy));
                    uint32_t hi2 = bf2_pack(hx, hy);
                    uint32_t lo2 = bf2_pack(vx - hx, vy - hy);
                    int bb = m >> 11, s = m & 2047;
                    int hh = n >> 6,  d = n & 63;
                    size_t idx = ((((size_t)bb * H_ + hh) * S_ + s) << 6) + d;
                    *reinterpret_cast<uint32_t*>(&Cb[idx])        = hi2;
                    *reinterpret_cast<uint32_t*>(&Cb[QSZ_ + idx]) = lo2;
                }
            }
        }
    }
}

// ---------------------------------------------------------------------------
// Tensor-core flash attention (bf16x3) with ALiBi + causal mask
// grid = (S/64, H, B), block = 128 (4 warps). Warp owns 16 query rows.
// K tile = 64 keys per iteration. Q pre-scaled by 1/8 at projection time.
// smem rows: [hi(64) | lo(64)] bf16, stride 136 (conflict-free ldmatrix).
// ---------------------------------------------------------------------------
#define KST 136

__global__ __launch_bounds__(128)
void flash_tc(float* __restrict__ out)
{
    __shared__ __align__(16) __nv_bfloat16 sK[64 * KST];
    __shared__ __align__(16) __nv_bfloat16 sV[64 * KST];

    const int t = threadIdx.x;
    const int w = t >> 5, l = t & 31;
    const int qt = blockIdx.x, h = blockIdx.y, b = blockIdx.z;
    const size_t hd_base = ((size_t)b * H_ + h) * S_ * D_;

    const uint32_t sKa = smem_u32(sK);
    const uint32_t sVa = smem_u32(sV);

    const float slope = exp2f(-0.5f * (float)(h + 1));   // H=16 power of 2

    // ---- stage Q tile into sK, load persistent A-fragments
    {
        const uint4* qh4 = reinterpret_cast<const uint4*>(g_qb + hd_base + (size_t)qt * 64 * 64);
        const uint4* ql4 = reinterpret_cast<const uint4*>(g_qb + QSZ_ + hd_base + (size_t)qt * 64 * 64);
        #pragma unroll
        for (int i = 0; i < 4; i++) {
            int idx = t + i * 128;   // 0..511
            int row = idx >> 3, c8 = idx & 7;
            *reinterpret_cast<uint4*>(&sK[row * KST + c8 * 8])      = qh4[idx];
            *reinterpret_cast<uint4*>(&sK[row * KST + 64 + c8 * 8]) = ql4[idx];
        }
    }
    __syncthreads();

    uint32_t qhf[4][4], qlf[4][4];
    {
        uint32_t arow = (uint32_t)(w * 16 + (l & 15));
        uint32_t acol = (l & 16) ? 8u : 0u;
        #pragma unroll
        for (int kg = 0; kg < 4; kg++) {
            ldsm_x4(qhf[kg], sKa + (arow * KST + kg * 16 + acol) * 2);
            ldsm_x4(qlf[kg], sKa + (arow * KST + 64 + kg * 16 + acol) * 2);
        }
    }
    __syncthreads();

    // B-fragment lane addressing (validated in R3 GEMM)
    const uint32_t brow  = (uint32_t)((l & 7) + ((l & 16) ? 8 : 0));
    const uint32_t bkoff = (l & 8) ? 8u : 0u;
    const uint32_t vrow  = (uint32_t)(l & 15);
    const uint32_t vcoff = (l & 16) ? 8u : 0u;

    const int qi0 = qt * 64 + w * 16 + (l >> 2);
    const int qi1 = qi0 + 8;
    const float rowb0 = slope * (float)qi0;
    const float rowb1 = slope * (float)qi1;

    float oacc[8][4];
    #pragma unroll
    for (int i = 0; i < 8; i++) {
        oacc[i][0] = 0.f; oacc[i][1] = 0.f; oacc[i][2] = 0.f; oacc[i][3] = 0.f;
    }
    float mst0 = -1e30f, mst1 = -1e30f, ls0 = 0.f, ls1 = 0.f;

    for (int kt = 0; kt <= qt; kt++) {
        // ---- load K/V bf16 tiles (hi|lo)
        {
            const uint4* kh4 = reinterpret_cast<const uint4*>(g_kb + hd_base + (size_t)kt * 64 * 64);
            const uint4* kl4 = reinterpret_cast<const uint4*>(g_kb + QSZ_ + hd_base + (size_t)kt * 64 * 64);
            const uint4* vh4 = reinterpret_cast<const uint4*>(g_vb + hd_base + (size_t)kt * 64 * 64);
            const uint4* vl4 = reinterpret_cast<const uint4*>(g_vb + QSZ_ + hd_base + (size_t)kt * 64 * 64);
            #pragma unroll
            for (int i = 0; i < 4; i++) {
                int idx = t + i * 128;
                int row = idx >> 3, c8 = idx & 7;
                *reinterpret_cast<uint4*>(&sK[row * KST + c8 * 8])      = kh4[idx];
                *reinterpret_cast<uint4*>(&sK[row * KST + 64 + c8 * 8]) = kl4[idx];
                *reinterpret_cast<uint4*>(&sV[row * KST + c8 * 8])      = vh4[idx];
                *reinterpret_cast<uint4*>(&sV[row * KST + 64 + c8 * 8]) = vl4[idx];
            }
        }
        __syncthreads();

        // ---- S = Q K^T (3-term: QhKh + QlKh + QhKl)
        float sacc[8][4];
        #pragma unroll
        for (int i = 0; i < 8; i++) {
            sacc[i][0] = 0.f; sacc[i][1] = 0.f; sacc[i][2] = 0.f; sacc[i][3] = 0.f;
        }
        #pragma unroll
        for (int kg = 0; kg < 4; kg++) {
            #pragma unroll
            for (int nb2 = 0; nb2 < 4; nb2++) {
                uint32_t bh[4], bl[4];
                ldsm_x4(bh, sKa + ((nb2 * 16 + brow) * KST + kg * 16 + bkoff) * 2);
                mma_bf16(sacc[2 * nb2],     qhf[kg], bh[0], bh[1]);
                mma_bf16(sacc[2 * nb2 + 1], qhf[kg], bh[2], bh[3]);
                mma_bf16(sacc[2 * nb2],     qlf[kg], bh[0], bh[1]);
                mma_bf16(sacc[2 * nb2 + 1], qlf[kg], bh[2], bh[3]);
                ldsm_x4(bl, sKa + ((nb2 * 16 + brow) * KST + 64 + kg * 16 + bkoff) * 2);
                mma_bf16(sacc[2 * nb2],     qhf[kg], bl[0], bl[1]);
                mma_bf16(sacc[2 * nb2 + 1], qhf[kg], bl[2], bl[3]);
            }
        }

        // ---- ALiBi bias + causal mask + online softmax
        const int kjb = kt * 64 + 2 * (l & 3);
        float rm0 = -1e30f, rm1 = -1e30f;
        #pragma unroll
        for (int nb = 0; nb < 8; nb++) {
            int kj0 = kjb + nb * 8;
            float f0 = slope * (float)kj0;
            float f1 = f0 + slope;
            float v00 = sacc[nb][0] + f0 - rowb0;
            float v01 = sacc[nb][1] + f1 - rowb0;
            float v10 = sacc[nb][2] + f0 - rowb1;
            float v11 = sacc[nb][3] + f1 - rowb1;
            if (kt == qt) {
                if (kj0     > qi0) v00 = -1e30f;
                if (kj0 + 1 > qi0) v01 = -1e30f;
                if (kj0     > qi1) v10 = -1e30f;
                if (kj0 + 1 > qi1) v11 = -1e30f;
            }
            sacc[nb][0] = v00; sacc[nb][1] = v01;
            sacc[nb][2] = v10; sacc[nb][3] = v11;
            rm0 = fmaxf(rm0, fmaxf(v00, v01));
            rm1 = fmaxf(rm1, fmaxf(v10, v11));
        }
        rm0 = fmaxf(rm0, __shfl_xor_sync(0xffffffffu, rm0, 1));
        rm0 = fmaxf(rm0, __shfl_xor_sync(0xffffffffu, rm0, 2));
        rm1 = fmaxf(rm1, __shfl_xor_sync(0xffffffffu, rm1, 1));
        rm1 = fmaxf(rm1, __shfl_xor_sync(0xffffffffu, rm1, 2));

        float mn0 = fmaxf(mst0, rm0), mn1 = fmaxf(mst1, rm1);
        float al0 = __expf(mst0 - mn0), al1 = __expf(mst1 - mn1);
        mst0 = mn0; mst1 = mn1;

        float rs0 = 0.f, rs1 = 0.f;
        #pragma unroll
        for (int nb = 0; nb < 8; nb++) {
            float p00 = __expf(sacc[nb][0] - mn0);
            float p01 = __expf(sacc[nb][1] - mn0);
            float p10 = __expf(sacc[nb][2] - mn1);
            float p11 = __expf(sacc[nb][3] - mn1);
            sacc[nb][0] = p00; sacc[nb][1] = p01;
            sacc[nb][2] = p10; sacc[nb][3] = p11;
            rs0 += p00 + p01;
            rs1 += p10 + p11;
        }
        rs0 += __shfl_xor_sync(0xffffffffu, rs0, 1);
        rs0 += __shfl_xor_sync(0xffffffffu, rs0, 2);
        rs1 += __shfl_xor_sync(0xffffffffu, rs1, 1);
        rs1 += __shfl_xor_sync(0xffffffffu, rs1, 2);
        ls0 = ls0 * al0 + rs0;
        ls1 = ls1 * al1 + rs1;

        #pragma unroll
        for (int nd = 0; nd < 8; nd++) {
            oacc[nd][0] *= al0; oacc[nd][1] *= al0;
            oacc[nd][2] *= al1; oacc[nd][3] *= al1;
        }

        // ---- O += P V (3-term: PhVh + PlVh + PhVl); P frags from S C-frags
        #pragma unroll
        for (int kg = 0; kg < 4; kg++) {
            float p00 = sacc[2 * kg][0],     p01 = sacc[2 * kg][1];
            float p10 = sacc[2 * kg][2],     p11 = sacc[2 * kg][3];
            float p20 = sacc[2 * kg + 1][0], p21 = sacc[2 * kg + 1][1];
            float p30 = sacc[2 * kg + 1][2], p31 = sacc[2 * kg + 1][3];
            float h00 = __bfloat162float(__float2bfloat16_rn(p00));
            float h01 = __bfloat162float(__float2bfloat16_rn(p01));
            float h10 = __bfloat162float(__float2bfloat16_rn(p10));
            float h11 = __bfloat162float(__float2bfloat16_rn(p11));
            float h20 = __bfloat162float(__float2bfloat16_rn(p20));
            float h21 = __bfloat162float(__float2bfloat16_rn(p21));
            float h30 = __bfloat162float(__float2bfloat16_rn(p30));
            float h31 = __bfloat162float(__float2bfloat16_rn(p31));
            uint32_t ah[4], alo[4];
            ah[0]  = bf2_pack(h00, h01);
            ah[1]  = bf2_pack(h10, h11);
            ah[2]  = bf2_pack(h20, h21);
            ah[3]  = bf2_pack(h30, h31);
            alo[0] = bf2_pack(p00 - h00, p01 - h01);
            alo[1] = bf2_pack(p10 - h10, p11 - h11);
            alo[2] = bf2_pack(p20 - h20, p21 - h21);
            alo[3] = bf2_pack(p30 - h30, p31 - h31);

            #pragma unroll
            for (int nd2 = 0; nd2 < 4; nd2++) {
                uint32_t vh[4], vl[4];
                ldsm_x4_t(vh, sVa + ((kg * 16 + vrow) * KST + nd2 * 16 + vcoff) * 2);
                mma_bf16(oacc[2 * nd2],     ah,  vh[0], vh[1]);
                mma_bf16(oacc[2 * nd2 + 1], ah,  vh[2], vh[3]);
                mma_bf16(oacc[2 * nd2],     alo, vh[0], vh[1]);
                mma_bf16(oacc[2 * nd2 + 1], alo, vh[2], vh[3]);
                ldsm_x4_t(vl, sVa + ((kg * 16 + vrow) * KST + 64 + nd2 * 16 + vcoff) * 2);
                mma_bf16(oacc[2 * nd2],     ah,  vl[0], vl[1]);
                mma_bf16(oacc[2 * nd2 + 1], ah,  vl[2], vl[3]);
            }
        }
        __syncthreads();
    }

    // ---- normalize + write [B,S,E]
    const float inv0 = 1.f / ls0, inv1 = 1.f / ls1;
    const int row0 = qt * 64 + w * 16 + (l >> 2);
    #pragma unroll
    for (int nd = 0; nd < 8; nd++) {
        int col = h * 64 + nd * 8 + 2 * (l & 3);
        float2 o0; o0.x = oacc[nd][0] * inv0; o0.y = oacc[nd][1] * inv0;
        float2 o1; o1.x = oacc[nd][2] * inv1; o1.y = oacc[nd][3] * inv1;
        *reinterpret_cast<float2*>(&out[((size_t)b * S_ + row0) * E_ + col])     = o0;
        *reinterpret_cast<float2*>(&out[((size_t)b * S_ + row0 + 8) * E_ + col]) = o1;
    }
}

// ---------------------------------------------------------------------------
extern "C" void kernel_launch(void* const* d_in, const int* in_sizes, int n_in,
                              void* d_out, int out_size)
{
    const float* x  = (const float*)d_in[0];
    const float* Wq = (const float*)d_in[1];
    const float* bq = (const float*)d_in[2];
    const float* Wk = (const float*)d_in[3];
    const float* bk = (const float*)d_in[4];
    const float* Wv = (const float*)d_in[5];
    const float* bv = (const float*)d_in[6];
    const float* Wo = (const float*)d_in[7];
    const float* bo = (const float*)d_in[8];
    float* out = (float*)d_out;

    void *qp, *kp, *vp, *ap;
    cudaGetSymbolAddress(&qp, g_qb);
    cudaGetSymbolAddress(&kp, g_kb);
    cudaGetSymbolAddress(&vp, g_vb);
    cudaGetSymbolAddress(&ap, g_attn);

    const int SMEM_GEMM = 2 * SAB;   // 36864 B
    cudaFuncSetAttribute(hmma_gemm<0>, cudaFuncAttributeMaxDynamicSharedMemorySize, SMEM_GEMM);
    cudaFuncSetAttribute(hmma_gemm<1>, cudaFuncAttributeMaxDynamicSharedMemorySize, SMEM_GEMM);

    // fused Q/K/V projections (bf16 hi/lo out, Q pre-scaled by 1/8)
    dim3 qkv_grid(E_ / 128, MTOT / 128, 3);
    hmma_gemm<1><<<qkv_grid, 256, SMEM_GEMM>>>(x, Wq, Wk, Wv, bq, bk, bv, qp, kp, vp);

    // tensor-core flash attention
    dim3 fgrid(S_ / 64, H_, B_);
    flash_tc<<<fgrid, 128>>>((float*)ap);

    // output projection (fp32 out)
    dim3 o_grid(E_ / 128, MTOT / 128, 1);
    hmma_gemm<0><<<o_grid, 256, SMEM_GEMM>>>((const float*)ap, Wo, Wo, Wo, bo, bo, bo,
                                             d_out, d_out, d_out);
}